// round 6
// baseline (speedup 1.0000x reference)
#include <cuda_runtime.h>

#define NN 50000
#define EE 400000
#define EPSBN 1e-5f

// ---------------- scratch (device globals: allocation-free) ----------------
__device__ float g_s[(size_t)NN * 128];     // GEMM output ("support")
__device__ float g_h[(size_t)NN * 128];     // aggregated gcn output
__device__ float g_inp[(size_t)NN * 128];   // residual input
__device__ float g_t[(size_t)NN * 128];     // mixed input to GEMM
__device__ float g_alpha[NN];
__device__ __align__(16) float g_stats[256]; // [0:128) sum, [128:256) sumsq

// CSR (rebuilt every launch; g_deg left zeroed by scan3 for the next launch;
// zero-initialized at module load for the very first run)
__device__ int   g_deg[NN];
__device__ int   g_rowPtr[NN + 1];
__device__ int   g_cursor[NN];
__device__ int   g_blkSum[256];
__device__ int   g_csrSrc[EE];
__device__ float g_csrW[EE];

// ---------------- packed fp32x2 helpers ------------------------------------
__device__ __forceinline__ unsigned long long pack2(float v) {
    unsigned long long r;
    asm("mov.b64 %0, {%1, %1};" : "=l"(r) : "f"(v));
    return r;
}
__device__ __forceinline__ void ffma2(unsigned long long& d,
                                      unsigned long long a,
                                      unsigned long long b) {
    asm("fma.rn.f32x2 %0, %1, %2, %0;" : "+l"(d) : "l"(a), "l"(b));
}

// ================= CSR build =================
__global__ __launch_bounds__(256) void hist_k(const int* __restrict__ dst)
{
    int e = blockIdx.x * blockDim.x + threadIdx.x;
    if (e < EE) atomicAdd(&g_deg[__ldg(&dst[e])], 1);
}

__global__ __launch_bounds__(256) void scan1_k()
{
    __shared__ int sh[256];
    int tid = threadIdx.x;
    int i = blockIdx.x * 256 + tid;
    int v = (i < NN) ? g_deg[i] : 0;
    sh[tid] = v; __syncthreads();
    #pragma unroll
    for (int off = 1; off < 256; off <<= 1) {
        int add = (tid >= off) ? sh[tid - off] : 0;
        __syncthreads();
        sh[tid] += add;
        __syncthreads();
    }
    if (i < NN) g_rowPtr[i + 1] = sh[tid];
    if (tid == 255) g_blkSum[blockIdx.x] = sh[255];
}

// Absorbs the old scan2: each block reduces blkSum[0..blockIdx) itself.
// Also computes cursors and re-zeroes g_deg for the next launch.
__global__ __launch_bounds__(256) void scan3_k(int nBlk)
{
    __shared__ int sh[256];
    int tid = threadIdx.x;
    int lim = (blockIdx.x < nBlk) ? blockIdx.x : nBlk;
    sh[tid] = (tid < lim) ? g_blkSum[tid] : 0;
    __syncthreads();
    #pragma unroll
    for (int off = 128; off >= 1; off >>= 1) {
        if (tid < off) sh[tid] += sh[tid + off];
        __syncthreads();
    }
    int blkOff = sh[0];
    int i = blockIdx.x * 256 + tid;
    if (i < NN) {
        int d = g_deg[i];
        int incl = g_rowPtr[i + 1] + blkOff;
        g_rowPtr[i + 1] = incl;
        g_cursor[i] = incl - d;   // row start
        g_deg[i] = 0;             // leave clean for next launch
    }
    if (i == 0) g_rowPtr[0] = 0;
}

__global__ __launch_bounds__(256) void fill_k(const int* __restrict__ src,
                                              const int* __restrict__ dst,
                                              const float* __restrict__ ew)
{
    int e = blockIdx.x * blockDim.x + threadIdx.x;
    if (e < EE) {
        int d = __ldg(&dst[e]);
        int pos = atomicAdd(&g_cursor[d], 1);
        g_csrSrc[pos] = __ldg(&src[e]);
        g_csrW[pos] = __ldg(&ew[e]);
    }
}

// ================= GEMM: g_s[M, ldo] = A[M,128] @ W[128,Nout] ==============
// Tile: 64 rows x (16*TN) cols, 256 threads, 4xTN per thread, k-chunk 32.
// Inner product uses packed fma.rn.f32x2 (2 FMA / instruction).
// mode: A!=nullptr -> use A; else mode==1 -> g_inp, mode==0 -> g_t.
// Block (0,0,0) zeroes g_stats for the following aggregation.
template<int TN, int OCC>
__global__ __launch_bounds__(256, OCC) void gemm_k(
    const float* __restrict__ A, long aBatch, int mode,
    const float* __restrict__ W, long wBatch,
    int colOffPerBatch, int ldo, int M, int Nout)
{
    constexpr int TC = 16 * TN;          // tile cols
    constexpr int TN2 = TN / 2;
    __shared__ float As[32][68];         // k-major, padded
    __shared__ float Ws[32][TC];
    int tid = threadIdx.x;
    if (blockIdx.x == 0 && blockIdx.y == 0 && blockIdx.z == 0 && tid < 256)
        g_stats[tid] = 0.f;
    if (A == nullptr) A = mode ? g_inp : g_t;
    int b = blockIdx.z;
    A += (size_t)b * aBatch;
    W += (size_t)b * wBatch;
    int rowBase = blockIdx.y * 64;
    int colBase = blockIdx.x * TC;
    int tx = tid & 15, ty = tid >> 4;

    unsigned long long acc2[4][TN2] = {};
    #pragma unroll
    for (int k0 = 0; k0 < 128; k0 += 32) {
        // A tile: 64 rows x 32 k -> k-major smem (transpose on store)
        #pragma unroll
        for (int j = 0; j < 2; j++) {
            int idx = tid + j * 256;
            int r = idx >> 3, kq = idx & 7;
            int gr = rowBase + r;
            float4 v = make_float4(0.f, 0.f, 0.f, 0.f);
            if (gr < M) v = *(const float4*)(A + (size_t)gr * 128 + k0 + kq * 4);
            As[kq * 4 + 0][r] = v.x; As[kq * 4 + 1][r] = v.y;
            As[kq * 4 + 2][r] = v.z; As[kq * 4 + 3][r] = v.w;
        }
        // W tile: 32 k x TC cols
        #pragma unroll
        for (int j = 0; j < TN / 2; j++) {
            int idx = tid + j * 256;
            int kk = idx / (TC / 4), c4 = idx % (TC / 4);
            float4 v = *(const float4*)(W + (size_t)(k0 + kk) * Nout + colBase + c4 * 4);
            *(float4*)&Ws[kk][c4 * 4] = v;
        }
        __syncthreads();
        #pragma unroll
        for (int k = 0; k < 32; k++) {
            float a[4];
            *(float4*)&a[0] = *(const float4*)&As[k][ty * 4];
            unsigned long long w2[TN2];
            {
                const unsigned long long* wp =
                    (const unsigned long long*)&Ws[k][tx * TN];
                #pragma unroll
                for (int c = 0; c < TN2; c++) w2[c] = wp[c];
            }
            #pragma unroll
            for (int r = 0; r < 4; r++) {
                unsigned long long a2 = pack2(a[r]);
                #pragma unroll
                for (int c = 0; c < TN2; c++)
                    ffma2(acc2[r][c], a2, w2[c]);
            }
        }
        __syncthreads();
    }
    int colOff = colBase + b * colOffPerBatch + tx * TN;
    #pragma unroll
    for (int r = 0; r < 4; r++) {
        int gr = rowBase + ty * 4 + r;
        if (gr < M) {
            unsigned long long* p =
                (unsigned long long*)(g_s + (size_t)gr * ldo + colOff);
            #pragma unroll
            for (int c = 0; c < TN2; c++) p[c] = acc2[r][c];
        }
    }
}

// ================= aggregation: h[row] = sum_e w_e * s[src_e] ==============
__global__ __launch_bounds__(256) void agg128_k()
{
    int tid = threadIdx.x;
    int lane = tid & 31;
    int wid = tid >> 5;
    int warp = (blockIdx.x * blockDim.x + tid) >> 5;
    int nWarps = (gridDim.x * blockDim.x) >> 5;

    float4 sum = make_float4(0.f, 0.f, 0.f, 0.f);
    float4 sq  = make_float4(0.f, 0.f, 0.f, 0.f);

    for (int row = warp; row < NN; row += nWarps) {
        int e = __ldg(&g_rowPtr[row]);
        int end = __ldg(&g_rowPtr[row + 1]);
        float4 acc = make_float4(0.f, 0.f, 0.f, 0.f);
        for (; e + 3 < end; e += 4) {
            int   s0 = __ldg(&g_csrSrc[e]),     s1 = __ldg(&g_csrSrc[e + 1]);
            int   s2 = __ldg(&g_csrSrc[e + 2]), s3 = __ldg(&g_csrSrc[e + 3]);
            float w0 = __ldg(&g_csrW[e]),       w1 = __ldg(&g_csrW[e + 1]);
            float w2 = __ldg(&g_csrW[e + 2]),   w3 = __ldg(&g_csrW[e + 3]);
            float4 v0 = ((const float4*)(g_s + (size_t)s0 * 128))[lane];
            float4 v1 = ((const float4*)(g_s + (size_t)s1 * 128))[lane];
            float4 v2 = ((const float4*)(g_s + (size_t)s2 * 128))[lane];
            float4 v3 = ((const float4*)(g_s + (size_t)s3 * 128))[lane];
            acc.x += w0 * v0.x + w1 * v1.x + w2 * v2.x + w3 * v3.x;
            acc.y += w0 * v0.y + w1 * v1.y + w2 * v2.y + w3 * v3.y;
            acc.z += w0 * v0.z + w1 * v1.z + w2 * v2.z + w3 * v3.z;
            acc.w += w0 * v0.w + w1 * v1.w + w2 * v2.w + w3 * v3.w;
        }
        for (; e < end; e++) {
            int s0 = __ldg(&g_csrSrc[e]);
            float w0 = __ldg(&g_csrW[e]);
            float4 v0 = ((const float4*)(g_s + (size_t)s0 * 128))[lane];
            acc.x += w0 * v0.x; acc.y += w0 * v0.y;
            acc.z += w0 * v0.z; acc.w += w0 * v0.w;
        }
        ((float4*)(g_h + (size_t)row * 128))[lane] = acc;
        sum.x += acc.x; sum.y += acc.y; sum.z += acc.z; sum.w += acc.w;
        sq.x += acc.x * acc.x; sq.y += acc.y * acc.y;
        sq.z += acc.z * acc.z; sq.w += acc.w * acc.w;
    }

    __shared__ float4 shs[8][32], shq[8][32];
    shs[wid][lane] = sum; shq[wid][lane] = sq;
    __syncthreads();
    #pragma unroll
    for (int off = 4; off >= 1; off >>= 1) {
        if (wid < off) {
            float4 a = shs[wid][lane], b = shs[wid + off][lane];
            a.x += b.x; a.y += b.y; a.z += b.z; a.w += b.w;
            shs[wid][lane] = a;
            float4 c = shq[wid][lane], d = shq[wid + off][lane];
            c.x += d.x; c.y += d.y; c.z += d.z; c.w += d.w;
            shq[wid][lane] = c;
        }
        __syncthreads();
    }
    if (wid == 0) {
        float4 a = shs[0][lane], c = shq[0][lane];
        int col = lane * 4;
        atomicAdd(&g_stats[col + 0], a.x);
        atomicAdd(&g_stats[col + 1], a.y);
        atomicAdd(&g_stats[col + 2], a.z);
        atomicAdd(&g_stats[col + 3], a.w);
        atomicAdd(&g_stats[128 + col + 0], c.x);
        atomicAdd(&g_stats[128 + col + 1], c.y);
        atomicAdd(&g_stats[128 + col + 2], c.z);
        atomicAdd(&g_stats[128 + col + 3], c.w);
    }
}

// final: aggregate 64-wide from g_s, add b_last, fused log_softmax -> out
__global__ __launch_bounds__(256) void agg64_softmax_k(const float* __restrict__ bLast,
                                                       float* __restrict__ out)
{
    int tid = threadIdx.x;
    int lane = tid & 31;
    int warp = (blockIdx.x * blockDim.x + tid) >> 5;
    int nWarps = (gridDim.x * blockDim.x) >> 5;
    float2 bias = ((const float2*)bLast)[lane];

    for (int row = warp; row < NN; row += nWarps) {
        int e = __ldg(&g_rowPtr[row]);
        int end = __ldg(&g_rowPtr[row + 1]);
        float2 acc = bias;
        for (; e + 3 < end; e += 4) {
            int   s0 = __ldg(&g_csrSrc[e]),     s1 = __ldg(&g_csrSrc[e + 1]);
            int   s2 = __ldg(&g_csrSrc[e + 2]), s3 = __ldg(&g_csrSrc[e + 3]);
            float w0 = __ldg(&g_csrW[e]),       w1 = __ldg(&g_csrW[e + 1]);
            float w2 = __ldg(&g_csrW[e + 2]),   w3 = __ldg(&g_csrW[e + 3]);
            float2 v0 = ((const float2*)(g_s + (size_t)s0 * 64))[lane];
            float2 v1 = ((const float2*)(g_s + (size_t)s1 * 64))[lane];
            float2 v2 = ((const float2*)(g_s + (size_t)s2 * 64))[lane];
            float2 v3 = ((const float2*)(g_s + (size_t)s3 * 64))[lane];
            acc.x += w0 * v0.x + w1 * v1.x + w2 * v2.x + w3 * v3.x;
            acc.y += w0 * v0.y + w1 * v1.y + w2 * v2.y + w3 * v3.y;
        }
        for (; e < end; e++) {
            int s0 = __ldg(&g_csrSrc[e]);
            float w0 = __ldg(&g_csrW[e]);
            float2 v0 = ((const float2*)(g_s + (size_t)s0 * 64))[lane];
            acc.x += w0 * v0.x; acc.y += w0 * v0.y;
        }
        float m = fmaxf(acc.x, acc.y);
        #pragma unroll
        for (int o = 16; o; o >>= 1) m = fmaxf(m, __shfl_xor_sync(0xFFFFFFFFu, m, o));
        float s = expf(acc.x - m) + expf(acc.y - m);
        #pragma unroll
        for (int o = 16; o; o >>= 1) s += __shfl_xor_sync(0xFFFFFFFFu, s, o);
        float l = m + logf(s);
        ((float2*)(out + (size_t)row * 64))[lane] = make_float2(acc.x - l, acc.y - l);
    }
}

// ================= fused BN + gate kernels =================
__device__ __forceinline__ float4 bn_relu4(float4 h, int cg) {
    float4 su = ((const float4*)g_stats)[cg];
    float4 sq = ((const float4*)g_stats)[32 + cg];
    const float invN = 1.f / NN;
    float4 o;
    float mu, var;
    mu = su.x * invN; var = sq.x * invN - mu * mu;
    o.x = fmaxf((h.x - mu) * rsqrtf(var + EPSBN), 0.f);
    mu = su.y * invN; var = sq.y * invN - mu * mu;
    o.y = fmaxf((h.y - mu) * rsqrtf(var + EPSBN), 0.f);
    mu = su.z * invN; var = sq.z * invN - mu * mu;
    o.z = fmaxf((h.z - mu) * rsqrtf(var + EPSBN), 0.f);
    mu = su.w * invN; var = sq.w * invN - mu * mu;
    o.w = fmaxf((h.w - mu) * rsqrtf(var + EPSBN), 0.f);
    return o;
}

// inp = relu(bn(h)); (first mix is identity: t == inp, GEMM reads g_inp)
__global__ __launch_bounds__(256) void fuse_first_k()
{
    int warp = (blockIdx.x * blockDim.x + threadIdx.x) >> 5;
    if (warp >= NN) return;
    int lane = threadIdx.x & 31;
    size_t off = (size_t)warp * 32 + lane;
    float4 x = bn_relu4(((const float4*)g_h)[off], lane);
    ((float4*)g_inp)[off] = x;
}

__global__ __launch_bounds__(256) void fuse_mid_k(const float* __restrict__ linW,
                                                  const float* __restrict__ linb)
{
    int warp = (blockIdx.x * blockDim.x + threadIdx.x) >> 5;
    if (warp >= NN) return;
    int lane = threadIdx.x & 31;
    size_t off = (size_t)warp * 32 + lane;
    float4 x = bn_relu4(((const float4*)g_h)[off], lane);
    float4 ii = ((const float4*)g_inp)[off];
    float4 w1 = ((const float4*)linW)[lane];
    float4 w2 = ((const float4*)(linW + 128))[lane];
    float d = ii.x * w1.x + ii.y * w1.y + ii.z * w1.z + ii.w * w1.w
            + x.x * w2.x + x.y * w2.y + x.z * w2.z + x.w * w2.w;
    #pragma unroll
    for (int o = 16; o; o >>= 1) d += __shfl_xor_sync(0xFFFFFFFFu, d, o);
    float a = 1.f / (1.f + expf(-(d + linb[0])));
    float4 tv;
    tv.x = a * x.x + (1.f - a) * ii.x;
    tv.y = a * x.y + (1.f - a) * ii.y;
    tv.z = a * x.z + (1.f - a) * ii.z;
    tv.w = a * x.w + (1.f - a) * ii.w;
    ((float4*)g_t)[off] = tv;
    if (lane == 0) g_alpha[warp] = a;
}

__global__ __launch_bounds__(256) void fuse_final_k()
{
    int warp = (blockIdx.x * blockDim.x + threadIdx.x) >> 5;
    if (warp >= NN) return;
    int lane = threadIdx.x & 31;
    size_t off = (size_t)warp * 32 + lane;
    float4 x = bn_relu4(((const float4*)g_h)[off], lane);
    float4 ii = ((const float4*)g_inp)[off];
    float a = g_alpha[warp];
    float4 tv;
    tv.x = a * x.x + (1.f - a) * ii.x;
    tv.y = a * x.y + (1.f - a) * ii.y;
    tv.z = a * x.z + (1.f - a) * ii.z;
    tv.w = a * x.w + (1.f - a) * ii.w;
    ((float4*)g_t)[off] = tv;
}

// ================= launch sequence =================
extern "C" void kernel_launch(void* const* d_in, const int* in_sizes, int n_in,
                              void* d_out, int out_size)
{
    const float* x_list = (const float*)d_in[0];   // [2, N, 128]
    const int*   esrc   = (const int*)d_in[1];
    const int*   edst   = (const int*)d_in[2];
    const float* ew     = (const float*)d_in[3];
    const float* W_init = (const float*)d_in[4];   // [2,128,64]
    const float* W_mid  = (const float*)d_in[6];   // [2,128,128]
    const float* W_last = (const float*)d_in[8];   // [128,64]
    const float* b_last = (const float*)d_in[9];   // [64]
    const float* linW   = (const float*)d_in[10];  // [256]
    const float* linb   = (const float*)d_in[11];  // [1]
    float* out = (float*)d_out;

    const int nScanBlk = (NN + 255) / 256;          // 196
    const int eBlk = (EE + 255) / 256;              // 1563
    const int rowsG = (NN + 63) / 64;               // 782
    const int blkWarpRow = (NN * 32 + 255) / 256;   // 6250
    const int aggBlk = 1184;

    // ---- CSR build (g_deg arrives zeroed from the previous launch) ----
    hist_k<<<eBlk, 256>>>(edst);
    scan1_k<<<nScanBlk, 256>>>();
    scan3_k<<<nScanBlk, 256>>>(nScanBlk);
    fill_k<<<eBlk, 256>>>(esrc, edst, ew);

    // ---- layer 1 (init GCNs, concat; bias cancels in BN) ----
    gemm_k<4, 6><<<dim3(1, rowsG, 2), 256>>>(x_list, (long)NN * 128, 0,
                                             W_init, (long)128 * 64, 64, 128, NN, 64);
    agg128_k<<<aggBlk, 256>>>();
    fuse_first_k<<<blkWarpRow, 256>>>();

    // ---- mid layer 0 (reads g_inp: first mix is identity) ----
    gemm_k<8, 4><<<dim3(1, rowsG, 1), 256>>>(nullptr, 0, 1,
                                             W_mid, 0, 0, 128, NN, 128);
    agg128_k<<<aggBlk, 256>>>();
    fuse_mid_k<<<blkWarpRow, 256>>>(linW, linb);

    // ---- mid layer 1 ----
    gemm_k<8, 4><<<dim3(1, rowsG, 1), 256>>>(nullptr, 0, 0,
                                             W_mid + (size_t)128 * 128, 0, 0, 128, NN, 128);
    agg128_k<<<aggBlk, 256>>>();
    fuse_final_k<<<blkWarpRow, 256>>>();

    // ---- last layer (bias + log_softmax fused into aggregation) ----
    gemm_k<4, 6><<<dim3(1, rowsG, 1), 256>>>(nullptr, 0, 0,
                                             W_last, 0, 0, 64, NN, 64);
    agg64_softmax_k<<<aggBlk, 256>>>(b_last, out);
}